// round 14
// baseline (speedup 1.0000x reference)
#include <cuda_runtime.h>
#include <math.h>

#define HH 256
#define WW 256
#define HWSZ 65536
#define BB 4
#define TILE_W 32
#define TILE_H 16
#define CBLK 2

typedef unsigned long long u64;

__device__ __forceinline__ u64 pack2(float v) {
    u64 r; asm("mov.b64 %0, {%1, %1};" : "=l"(r) : "f"(v)); return r;
}
__device__ __forceinline__ u64 ffma2(u64 a, u64 b, u64 c) {
    u64 d; asm("fma.rn.f32x2 %0, %1, %2, %3;" : "=l"(d) : "l"(a), "l"(b), "l"(c)); return d;
}
__device__ __forceinline__ void unpack2(u64 v, float& lo, float& hi) {
    asm("mov.b64 {%0, %1}, %2;" : "=f"(lo), "=f"(hi) : "l"(v));
}
__device__ __forceinline__ void cp4(void* smem_dst, const float* gsrc, unsigned pred) {
    unsigned saddr = (unsigned)__cvta_generic_to_shared(smem_dst);
    unsigned sz = pred ? 4u : 0u;
    asm volatile("cp.async.ca.shared.global [%0], [%1], 4, %2;\n"
                 :: "r"(saddr), "l"(gsrc), "r"(sz));
}
__device__ __forceinline__ void cp_commit() {
    asm volatile("cp.async.commit_group;" ::: "memory");
}
template<int N>
__device__ __forceinline__ void cp_wait() {
    asm volatile("cp.async.wait_group %0;" :: "n"(N) : "memory");
}

// ---- scratch (device globals: no allocation allowed) ----
__device__ float g_t1[BB * 16 * HWSZ];
__device__ float g_t2[BB * 16 * HWSZ];
__device__ float g_t3[BB * 16 * HWSZ];
__device__ float g_fEsa[BB * 16 * HWSZ];
__device__ float g_fEFsa[BB * 16 * HWSZ];
__device__ float g_fEdc[BB * 16 * HWSZ];
__device__ float g_fEFdc[BB * 16 * HWSZ];
__device__ float g_om[BB * 27 * HWSZ];

// smem layout constants (shared by all conv instantiations)
#define SROW (TILE_W + 3)                 // 35: odd -> conflict-free
#define SCH  ((TILE_H + 2) * SROW)        // 630
#define SMEM_IN_BYTES (3 * CBLK * SCH * 4)        // 15120
#define SMEM_W_MAX    (32 * 9 * 16 * 4)           // 18432 (>= 16*9*28*4)
#define SMEM_MAX      (SMEM_IN_BYTES + SMEM_W_MAX)

// ============================================================================
// Direct 3x3 conv BODY, SAME padding (round-6 inner loop, unchanged).
// Takes logical (tx, ty, yblk) so callers with different block shapes can map
// a flat 128-thread block onto the (8,16) conv layout.
// ============================================================================
template<int CIN, int COUT, int ACT, bool DUAL, bool ZSPLIT>
__device__ __forceinline__ void conv3x3_body(
    char* smem_raw,
    const float* __restrict__ src0,
    const float* __restrict__ src1,
    const float* __restrict__ aux,
    const float* __restrict__ wg,
    const float* __restrict__ bias,
    float* __restrict__ out,
    int cout_stride, int b, int tx, int ty, int yblk)
{
    constexpr int PX = 4;
    constexpr int COUT_PAD = (COUT + 1) & ~1;
    constexpr int NPAIR_TOT = COUT_PAD / 2;
    constexpr int NPH = ZSPLIT ? (NPAIR_TOT + 1) / 2 : NPAIR_TOT;
    constexpr int C0 = DUAL ? 16 : CIN;
    constexpr int NT = (TILE_W / PX) * TILE_H * (ZSPLIT ? 2 : 1);
    constexpr int NSTAGE = CIN / CBLK;
    constexpr int HALO = (TILE_H + 2) * (TILE_W + 2);   // 612
    constexpr int NPOS = (HALO + NT - 1) / NT;

    float (*s_in)[CBLK * SCH] = (float (*)[CBLK * SCH])smem_raw;
    float* s_w = (float*)(smem_raw + SMEM_IN_BYTES);

    const int z = ZSPLIT ? threadIdx.z : 0;
    const int tid = (z * TILE_H + ty) * (TILE_W / PX) + tx;
    const int x0 = blockIdx.x * TILE_W, y0 = yblk * TILE_H;

    // ---- precompute per-thread halo positions (once) ----
    unsigned soff[NPOS];
    int poff[NPOS];
    unsigned okmask = 0;
#pragma unroll
    for (int i = 0; i < NPOS; i++) {
        int idx = tid + i * NT;
        if (i + 1 == NPOS && idx >= HALO) { soff[i] = 0; poff[i] = 0; continue; }
        int row = idx / (TILE_W + 2), col = idx - row * (TILE_W + 2);
        int gy = y0 - 1 + row, gx = x0 - 1 + col;
        unsigned ok = ((unsigned)gy < HH) & ((unsigned)gx < WW);
        soff[i] = row * SROW + col;
        poff[i] = (ok ? gy : 0) * WW + (ok ? gx : 0);
        okmask |= ok << i;
    }

    // ---- weight staging (transpose [co][ci][k] -> [ci][k][co_pad]) ----
    for (int idx = tid; idx < COUT * CIN * 9; idx += NT) {
        int co = idx / (CIN * 9);
        int r = idx - co * (CIN * 9);
        int ci = r / 9, k = r - ci * 9;
        cp4(&s_w[(ci * 9 + k) * COUT_PAD + co], &wg[idx], 1u);
    }
    if (COUT & 1) {
        for (int idx = tid; idx < CIN * 9; idx += NT)
            s_w[idx * COUT_PAD + COUT] = 0.f;
    }

    // ---- channel-block staging with precomputed offsets ----
    auto stage_load = [&](int sidx, int buf) {
        const int cb = sidx * CBLK;
        const float* bp;
        if (!DUAL || cb < 16) bp = src0 + ((size_t)b * C0 + cb) * HWSZ;
        else                  bp = src1 + ((size_t)b * 16 + (cb - 16)) * HWSZ;
        float* sb = &s_in[buf][0];
#pragma unroll
        for (int c = 0; c < CBLK; c++) {
#pragma unroll
            for (int i = 0; i < NPOS; i++) {
                if (i + 1 < NPOS || tid < HALO - (NPOS - 1) * NT)
                    cp4(sb + c * SCH + soff[i], bp + c * HWSZ + poff[i],
                        (okmask >> i) & 1u);
            }
        }
    };

    u64 acc[NPH][PX];
#pragma unroll
    for (int p = 0; p < NPH; p++)
#pragma unroll
        for (int j = 0; j < PX; j++) acc[p][j] = 0ull;

    stage_load(0, 0);
    cp_commit();            // group 0: weights + stage 0
    stage_load(1, 1);
    cp_commit();            // group 1

    for (int s = 0; s < NSTAGE; s++) {
        if (s + 1 < NSTAGE) cp_wait<1>(); else cp_wait<0>();
        __syncthreads();
        if (s + 2 < NSTAGE) { stage_load(s + 2, (s + 2) % 3); cp_commit(); }

        const int buf = s % 3;
        const int cb = s * CBLK;

#pragma unroll 1
        for (int c = 0; c < CBLK; c++) {
            const int cin = cb + c;
            const float* base = &s_in[buf][c * SCH];
            u64 vv[3][PX + 2];
#pragma unroll
            for (int r = 0; r < 3; r++) {
                const float* rp = base + (ty + r) * SROW + tx * PX;
#pragma unroll
                for (int j = 0; j < PX + 2; j++)
                    vv[r][j] = pack2(rp[j]);
            }
            const u64* wp = (const u64*)s_w + cin * 9 * NPAIR_TOT + z * NPH;
#pragma unroll
            for (int k = 0; k < 9; k++) {
                const int ky = k / 3, kx = k - ky * 3;
#pragma unroll
                for (int p = 0; p < NPH; p++) {
                    if (z == 0 || NPH + p < NPAIR_TOT) {
                        u64 w2 = wp[k * NPAIR_TOT + p];
#pragma unroll
                        for (int j = 0; j < PX; j++)
                            acc[p][j] = ffma2(w2, vv[ky][kx + j], acc[p][j]);
                    }
                }
            }
        }
    }

    const int y = y0 + ty, xbase = x0 + tx * PX;

    if (ACT == 3) {
        // f_Esa epilogue: s = sigmoid(conv + bias); out[c] = aux[c] * s
        float sg[PX];
#pragma unroll
        for (int j = 0; j < PX; j++) {
            float lo, hi; unpack2(acc[0][j], lo, hi);
            lo += bias[0];
            sg[j] = 1.f / (1.f + expf(-lo));
        }
#pragma unroll 1
        for (int c = 0; c < 16; c++) {
            const float* src = aux + (((size_t)b * 16 + c) * HH + y) * WW + xbase;
            float* dst = out + (((size_t)b * 16 + c) * HH + y) * WW + xbase;
            float4 v = *(const float4*)src;
            v.x *= sg[0]; v.y *= sg[1]; v.z *= sg[2]; v.w *= sg[3];
            *(float4*)dst = v;
        }
        return;
    }

    // epilogue: bias + activation + vector store (own pair range only)
#pragma unroll
    for (int p = 0; p < NPH; p++) {
        if (!(z == 0 || NPH + p < NPAIR_TOT)) continue;
        const int pi = z * NPH + p;
        const int co0 = 2 * pi, co1 = 2 * pi + 1;
        const float b0 = bias[co0];
        const float b1 = (co1 < COUT) ? bias[co1] : 0.f;
        float o0[PX], o1[PX];
#pragma unroll
        for (int j = 0; j < PX; j++) {
            float lo, hi; unpack2(acc[p][j], lo, hi);
            lo += b0; hi += b1;
            if (ACT == 1) { lo = fmaxf(lo, 0.f); hi = fmaxf(hi, 0.f); }
            else if (ACT == 2) { lo = 1.f / (1.f + expf(-lo)); hi = 1.f / (1.f + expf(-hi)); }
            o0[j] = lo; o1[j] = hi;
        }
        float* q0 = out + ((size_t)(b * cout_stride + co0) * HH + y) * WW + xbase;
        *(float4*)q0 = make_float4(o0[0], o0[1], o0[2], o0[3]);
        if (co1 < COUT) {
            float* q1 = out + ((size_t)(b * cout_stride + co1) * HH + y) * WW + xbase;
            *(float4*)q1 = make_float4(o1[0], o1[1], o1[2], o1[3]);
        }
    }
}

// ============================================================================
// Deform conv BODY (torchvision semantics), 1 output pixel per thread, all 16
// Cout. Planar coalesced gather. NT = thread count of the calling block.
// ============================================================================
template<int NT>
__device__ __forceinline__ void deform_body(
    char* smem_raw,
    const float* __restrict__ fE,   // [B][16][H][W]
    const float* __restrict__ om,   // [B][27][H][W]
    const float* __restrict__ wg,   // [16][16][3][3]
    const float* __restrict__ bias, // [16]
    float* __restrict__ out,        // [B][16][H][W]
    int b, int x, int y, int tid)
{
    float* s_w = (float*)smem_raw;  // [ci][tap][co], 16*9*16 floats
    for (int idx = tid; idx < 16 * 16 * 9; idx += NT) {
        int co = idx / 144;
        int r = idx - co * 144;
        int ci = r / 9, t = r - ci * 9;
        s_w[(ci * 9 + t) * 16 + co] = wg[idx];
    }
    __syncthreads();

    u64 acc[8];
#pragma unroll
    for (int p = 0; p < 8; p++) acc[p] = 0ull;

    const float* omb = om + (size_t)b * 27 * HWSZ + y * WW + x;
    const float* pE = fE + (size_t)b * 16 * HWSZ;

#pragma unroll 1
    for (int t = 0; t < 9; t++) {
        const float oy = omb[(2 * t) * HWSZ];
        const float ox = omb[(2 * t + 1) * HWSZ];
        const float mv = omb[(18 + t) * HWSZ];
        const float m = 1.f / (1.f + expf(-mv));
        const float py = (float)(y + t / 3 - 1) + oy;
        const float px = (float)(x + t % 3 - 1) + ox;
        const float fy = floorf(py), fx = floorf(px);
        const int y0 = (int)fy, x0 = (int)fx;
        const float dy = py - fy, dx = px - fx;
        float w00 = (1.f - dy) * (1.f - dx) * m;
        float w01 = (1.f - dy) * dx * m;
        float w10 = dy * (1.f - dx) * m;
        float w11 = dy * dx * m;
        const bool vy0 = (unsigned)y0 < HH, vy1 = (unsigned)(y0 + 1) < HH;
        const bool vx0 = (unsigned)x0 < WW, vx1 = (unsigned)(x0 + 1) < WW;
        if (!(vy0 && vx0)) w00 = 0.f;
        if (!(vy0 && vx1)) w01 = 0.f;
        if (!(vy1 && vx0)) w10 = 0.f;
        if (!(vy1 && vx1)) w11 = 0.f;
        const int y0c = min(max(y0, 0), HH - 1), y1c = min(max(y0 + 1, 0), HH - 1);
        const int x0c = min(max(x0, 0), WW - 1), x1c = min(max(x0 + 1, 0), WW - 1);
        const int i00 = y0c * WW + x0c, i01 = y0c * WW + x1c;
        const int i10 = y1c * WW + x0c, i11 = y1c * WW + x1c;

        float v00[16], v01[16], v10[16], v11[16];
#pragma unroll
        for (int ci = 0; ci < 16; ci++) {
            const float* pc = pE + ci * HWSZ;
            v00[ci] = pc[i00];
            v01[ci] = pc[i01];
            v10[ci] = pc[i10];
            v11[ci] = pc[i11];
        }

#pragma unroll
        for (int ci = 0; ci < 16; ci++) {
            const float s = w00 * v00[ci] + w01 * v01[ci]
                          + w10 * v10[ci] + w11 * v11[ci];
            const u64 ss = pack2(s);
            const u64* wrow = (const u64*)s_w + (ci * 9 + t) * 8;
#pragma unroll
            for (int p = 0; p < 8; p++)
                acc[p] = ffma2(wrow[p], ss, acc[p]);
        }
    }

#pragma unroll
    for (int p = 0; p < 8; p++) {
        float lo, hi; unpack2(acc[p], lo, hi);
        lo = fmaxf(lo + bias[2 * p], 0.f);
        hi = fmaxf(hi + bias[2 * p + 1], 0.f);
        out[((size_t)(b * 16 + 2 * p) * HH + y) * WW + x] = lo;
        out[((size_t)(b * 16 + 2 * p + 1) * HH + y) * WW + x] = hi;
    }
}

// ---- single-conv kernel (PX=4, no z-split) ----
template<int CIN, int COUT, int ACT, bool DUAL>
__global__ void __launch_bounds__(128, 4)
conv_k(const float* __restrict__ src0, const float* __restrict__ src1,
       const float* __restrict__ aux, const float* __restrict__ wg,
       const float* __restrict__ bias, float* __restrict__ out, int cout_stride)
{
    __shared__ __align__(16) char raw[SMEM_MAX];
    conv3x3_body<CIN, COUT, ACT, DUAL, false>(raw, src0, src1, aux, wg, bias,
                                              out, cout_stride, blockIdx.z,
                                              threadIdx.x, threadIdx.y, blockIdx.y);
}

// ---- z-split conv kernel (PX=4, cout halves across threadIdx.z) ----
template<int CIN, int COUT, int ACT, bool DUAL>
__global__ void __launch_bounds__(256, 2)
conv_kz(const float* __restrict__ src0, const float* __restrict__ src1,
        const float* __restrict__ aux, const float* __restrict__ wg,
        const float* __restrict__ bias, float* __restrict__ out, int cout_stride)
{
    __shared__ __align__(16) char raw[SMEM_MAX];
    conv3x3_body<CIN, COUT, ACT, DUAL, true>(raw, src0, src1, aux, wg, bias,
                                             out, cout_stride, blockIdx.z,
                                             threadIdx.x, threadIdx.y, blockIdx.y);
}

// ---- pair kernel: two independent convs in one launch (block-granular) ----
template<int CINA, int COUTA, int ACTA, bool DUALA,
         int CINB, int COUTB, int ACTB, bool DUALB>
__global__ void __launch_bounds__(128, 4)
conv_pair(const float* __restrict__ a0, const float* __restrict__ a1,
          const float* __restrict__ aaux,
          const float* __restrict__ aw, const float* __restrict__ ab,
          float* __restrict__ ao,
          const float* __restrict__ b0, const float* __restrict__ b1,
          const float* __restrict__ baux,
          const float* __restrict__ bw, const float* __restrict__ bb,
          float* __restrict__ bo)
{
    __shared__ __align__(16) char raw[SMEM_MAX];
    if (blockIdx.z < BB)
        conv3x3_body<CINA, COUTA, ACTA, DUALA, false>(raw, a0, a1, aaux, aw, ab,
                                                      ao, 16, blockIdx.z,
                                                      threadIdx.x, threadIdx.y, blockIdx.y);
    else
        conv3x3_body<CINB, COUTB, ACTB, DUALB, false>(raw, b0, b1, baux, bw, bb,
                                                      bo, 16, blockIdx.z - BB,
                                                      threadIdx.x, threadIdx.y, blockIdx.y);
}

// ---- combined k3 (conv 32->16) + deform kernel; grid (8, 64, 5), blk (32,4) ----
// z < 4 : deform, batch b = z, pixel (bx*32+tx, by*4+ty)
// z == 4: conv k3, b = by/16, y-block = by%16
__global__ void __launch_bounds__(128, 4)
k3_deform_kernel(const float* __restrict__ fEsa, const float* __restrict__ fF,
                 const float* __restrict__ w3, const float* __restrict__ b3,
                 float* __restrict__ fEFsa,
                 const float* __restrict__ fE, const float* __restrict__ om,
                 const float* __restrict__ dw, const float* __restrict__ db,
                 float* __restrict__ fEdc)
{
    __shared__ __align__(16) char raw[SMEM_MAX];
    const int tid = threadIdx.y * 32 + threadIdx.x;
    if (blockIdx.z < BB) {
        const int x = blockIdx.x * 32 + threadIdx.x;
        const int y = blockIdx.y * 4 + threadIdx.y;
        deform_body<128>(raw, fE, om, dw, db, fEdc, blockIdx.z, x, y, tid);
    } else {
        const int b = blockIdx.y >> 4;
        const int yblk = blockIdx.y & 15;
        conv3x3_body<32, 16, 1, true, false>(raw, fEsa, fF, nullptr, w3, b3,
                                             fEFsa, 16, b, tid % 8, tid / 8, yblk);
    }
}

// ============================================================================
// Launch
// ============================================================================
extern "C" void kernel_launch(void* const* d_in, const int* in_sizes, int n_in,
                              void* d_out, int out_size)
{
    const float* fE = (const float*)d_in[0];
    const float* fF = (const float*)d_in[1];
    const float* sab_att_w1 = (const float*)d_in[2];
    const float* sab_att_b1 = (const float*)d_in[3];
    const float* sab_att_w2 = (const float*)d_in[4];
    const float* sab_att_b2 = (const float*)d_in[5];
    const float* sab_ref_w = (const float*)d_in[6];
    const float* sab_ref_b = (const float*)d_in[7];
    const float* om_w1 = (const float*)d_in[8];
    const float* om_b1 = (const float*)d_in[9];
    const float* om_w2 = (const float*)d_in[10];
    const float* om_b2 = (const float*)d_in[11];
    const float* om_w3 = (const float*)d_in[12];
    const float* om_b3 = (const float*)d_in[13];
    const float* dcb_w = (const float*)d_in[14];
    const float* dcb_b = (const float*)d_in[15];
    const float* dcbref_w = (const float*)d_in[16];
    const float* dcbref_b = (const float*)d_in[17];
    const float* fin_w = (const float*)d_in[18];
    const float* fin_b = (const float*)d_in[19];
    float* out = (float*)d_out;

    float *t1, *t2, *t3, *fEsa, *fEFsa, *fEdc, *fEFdc, *om;
    cudaGetSymbolAddress((void**)&t1, g_t1);
    cudaGetSymbolAddress((void**)&t2, g_t2);
    cudaGetSymbolAddress((void**)&t3, g_t3);
    cudaGetSymbolAddress((void**)&fEsa, g_fEsa);
    cudaGetSymbolAddress((void**)&fEFsa, g_fEFsa);
    cudaGetSymbolAddress((void**)&fEdc, g_fEdc);
    cudaGetSymbolAddress((void**)&fEFdc, g_fEFdc);
    cudaGetSymbolAddress((void**)&om, g_om);

    dim3 grid(WW / TILE_W, HH / TILE_H, BB);       // (8, 16, 4)
    dim3 gridP(WW / TILE_W, HH / TILE_H, 2 * BB);  // (8, 16, 8) pair launches
    dim3 blk4(TILE_W / 4, TILE_H);                 // 128
    dim3 blkZ(TILE_W / 4, TILE_H, 2);              // 256 (z-split)
    dim3 gridKD(WW / TILE_W, 64, BB + 1);          // (8, 64, 5) k3+deform
    dim3 blkKD(32, 4);                             // 128

    // P1: t1 = relu(conv(cat(fE,fF), sab_att_w1)) ; t2 = relu(conv(cat(fE,fF), om_w1))
    conv_pair<32, 16, 1, true, 32, 16, 1, true><<<gridP, blk4>>>(
        fE, fF, nullptr, sab_att_w1, sab_att_b1, t1,
        fE, fF, nullptr, om_w1, om_b1, t2);
    // P2: f_Esa = fE*sigmoid(conv(t1, sab_att_w2)) ; t3 = relu(conv(t2, om_w2))
    conv_pair<16, 1, 3, false, 16, 16, 1, false><<<gridP, blk4>>>(
        t1, nullptr, fE, sab_att_w2, sab_att_b2, fEsa,
        t2, nullptr, nullptr, om_w2, om_b2, t3);
    // k6: om = conv(t3, om_w3)  [27 ch, no act] — PX=4 z-split
    conv_kz<16, 27, 0, false><<<grid, blkZ>>>(t3, nullptr, nullptr, om_w3, om_b3, om, 27);
    // P3: f_EFsa = relu(conv(cat(fEsa,fF), sab_ref_w)) ; f_Edc = relu(deform(fE, om, dcb))
    k3_deform_kernel<<<gridKD, blkKD>>>(
        fEsa, fF, sab_ref_w, sab_ref_b, fEFsa,
        fE, om, dcb_w, dcb_b, fEdc);
    // k8: f_EFdc = relu(conv(cat(fEdc, fF), dcbref_w))
    conv_k<32, 16, 1, true><<<grid, blk4>>>(fEdc, fF, nullptr, dcbref_w, dcbref_b, fEFdc, 16);
    // k9: out = relu(conv(cat(fEFsa, fEFdc), fin_w))
    conv_k<32, 16, 1, true><<<grid, blk4>>>(fEFsa, fEFdc, nullptr, fin_w, fin_b, out, 16);
}

// round 15
// speedup vs baseline: 1.0094x; 1.0094x over previous
#include <cuda_runtime.h>
#include <math.h>

#define HH 256
#define WW 256
#define HWSZ 65536
#define BB 4
#define TILE_W 32
#define TILE_H 16
#define CBLK 2

typedef unsigned long long u64;

__device__ __forceinline__ u64 pack2(float v) {
    u64 r; asm("mov.b64 %0, {%1, %1};" : "=l"(r) : "f"(v)); return r;
}
__device__ __forceinline__ u64 ffma2(u64 a, u64 b, u64 c) {
    u64 d; asm("fma.rn.f32x2 %0, %1, %2, %3;" : "=l"(d) : "l"(a), "l"(b), "l"(c)); return d;
}
__device__ __forceinline__ void unpack2(u64 v, float& lo, float& hi) {
    asm("mov.b64 {%0, %1}, %2;" : "=f"(lo), "=f"(hi) : "l"(v));
}
__device__ __forceinline__ void cp4(void* smem_dst, const float* gsrc, unsigned pred) {
    unsigned saddr = (unsigned)__cvta_generic_to_shared(smem_dst);
    unsigned sz = pred ? 4u : 0u;
    asm volatile("cp.async.ca.shared.global [%0], [%1], 4, %2;\n"
                 :: "r"(saddr), "l"(gsrc), "r"(sz));
}
__device__ __forceinline__ void cp_commit() {
    asm volatile("cp.async.commit_group;" ::: "memory");
}
template<int N>
__device__ __forceinline__ void cp_wait() {
    asm volatile("cp.async.wait_group %0;" :: "n"(N) : "memory");
}

// ---- scratch (device globals: no allocation allowed) ----
__device__ float g_t1[BB * 16 * HWSZ];
__device__ float g_t2[BB * 16 * HWSZ];
__device__ float g_t3[BB * 16 * HWSZ];
__device__ float g_ME[BB * HWSZ];
__device__ float g_fEFsa[BB * 16 * HWSZ];
__device__ float g_fEdc[BB * 16 * HWSZ];
__device__ float g_fEFdc[BB * 16 * HWSZ];
__device__ float g_om[BB * 27 * HWSZ];

// smem layout constants (shared by all conv instantiations)
#define SROW (TILE_W + 3)                 // 35: odd -> conflict-free
#define SCH  ((TILE_H + 2) * SROW)        // 630
#define SMEM_IN_BYTES (3 * CBLK * SCH * 4)        // 15120
#define SMEM_W_MAX    (32 * 9 * 16 * 4)           // 18432 (>= 16*9*28*4)
#define SMEM_MASK_OFF (SMEM_IN_BYTES + SMEM_W_MAX)
#define SMEM_MAX      (SMEM_MASK_OFF + SCH * 4)   // 36072

// ============================================================================
// Direct 3x3 conv BODY, SAME padding (round-6 inner loop).
// MASK: channels 0..15 of the input are multiplied by msk[b,1,H,W] at pack
// time (mask halo tile staged via cp.async into s_m).
// ACT: 0 none, 1 relu, 2 sigmoid.
// ============================================================================
template<int CIN, int COUT, int ACT, bool DUAL, bool ZSPLIT, bool MASK>
__device__ __forceinline__ void conv3x3_body(
    char* smem_raw,
    const float* __restrict__ src0,
    const float* __restrict__ src1,
    const float* __restrict__ msk,   // MASK: M_E [B][1][H][W]
    const float* __restrict__ wg,    // [COUT][CIN][3][3]
    const float* __restrict__ bias,  // [COUT]
    float* __restrict__ out,         // (pre-offset)
    int cout_stride, int b, int tx, int ty, int yblk)
{
    constexpr int PX = 4;
    constexpr int COUT_PAD = (COUT + 1) & ~1;
    constexpr int NPAIR_TOT = COUT_PAD / 2;
    constexpr int NPH = ZSPLIT ? (NPAIR_TOT + 1) / 2 : NPAIR_TOT;
    constexpr int C0 = DUAL ? 16 : CIN;
    constexpr int NT = (TILE_W / PX) * TILE_H * (ZSPLIT ? 2 : 1);
    constexpr int NSTAGE = CIN / CBLK;
    constexpr int HALO = (TILE_H + 2) * (TILE_W + 2);   // 612
    constexpr int NPOS = (HALO + NT - 1) / NT;

    float (*s_in)[CBLK * SCH] = (float (*)[CBLK * SCH])smem_raw;
    float* s_w = (float*)(smem_raw + SMEM_IN_BYTES);
    float* s_m = (float*)(smem_raw + SMEM_MASK_OFF);

    const int z = ZSPLIT ? threadIdx.z : 0;
    const int tid = (z * TILE_H + ty) * (TILE_W / PX) + tx;
    const int x0 = blockIdx.x * TILE_W, y0 = yblk * TILE_H;

    // ---- precompute per-thread halo positions (once) ----
    unsigned soff[NPOS];
    int poff[NPOS];
    unsigned okmask = 0;
#pragma unroll
    for (int i = 0; i < NPOS; i++) {
        int idx = tid + i * NT;
        if (i + 1 == NPOS && idx >= HALO) { soff[i] = 0; poff[i] = 0; continue; }
        int row = idx / (TILE_W + 2), col = idx - row * (TILE_W + 2);
        int gy = y0 - 1 + row, gx = x0 - 1 + col;
        unsigned ok = ((unsigned)gy < HH) & ((unsigned)gx < WW);
        soff[i] = row * SROW + col;
        poff[i] = (ok ? gy : 0) * WW + (ok ? gx : 0);
        okmask |= ok << i;
    }

    // ---- weight staging (transpose [co][ci][k] -> [ci][k][co_pad]) ----
    for (int idx = tid; idx < COUT * CIN * 9; idx += NT) {
        int co = idx / (CIN * 9);
        int r = idx - co * (CIN * 9);
        int ci = r / 9, k = r - ci * 9;
        cp4(&s_w[(ci * 9 + k) * COUT_PAD + co], &wg[idx], 1u);
    }
    if (COUT & 1) {
        for (int idx = tid; idx < CIN * 9; idx += NT)
            s_w[idx * COUT_PAD + COUT] = 0.f;
    }

    // ---- mask halo staging (MASK only; joins cp.async group 0) ----
    if (MASK) {
        const float* mb = msk + (size_t)b * HWSZ;
#pragma unroll
        for (int i = 0; i < NPOS; i++) {
            if (i + 1 < NPOS || tid < HALO - (NPOS - 1) * NT)
                cp4(s_m + soff[i], mb + poff[i], (okmask >> i) & 1u);
        }
    }

    // ---- channel-block staging with precomputed offsets ----
    auto stage_load = [&](int sidx, int buf) {
        const int cb = sidx * CBLK;
        const float* bp;
        if (!DUAL || cb < 16) bp = src0 + ((size_t)b * C0 + cb) * HWSZ;
        else                  bp = src1 + ((size_t)b * 16 + (cb - 16)) * HWSZ;
        float* sb = &s_in[buf][0];
#pragma unroll
        for (int c = 0; c < CBLK; c++) {
#pragma unroll
            for (int i = 0; i < NPOS; i++) {
                if (i + 1 < NPOS || tid < HALO - (NPOS - 1) * NT)
                    cp4(sb + c * SCH + soff[i], bp + c * HWSZ + poff[i],
                        (okmask >> i) & 1u);
            }
        }
    };

    u64 acc[NPH][PX];
#pragma unroll
    for (int p = 0; p < NPH; p++)
#pragma unroll
        for (int j = 0; j < PX; j++) acc[p][j] = 0ull;

    stage_load(0, 0);
    cp_commit();            // group 0: weights + mask + stage 0
    stage_load(1, 1);
    cp_commit();            // group 1

    for (int s = 0; s < NSTAGE; s++) {
        if (s + 1 < NSTAGE) cp_wait<1>(); else cp_wait<0>();
        __syncthreads();
        if (s + 2 < NSTAGE) { stage_load(s + 2, (s + 2) % 3); cp_commit(); }

        const int buf = s % 3;
        const int cb = s * CBLK;
        const bool domask = MASK && (cb < 16);

#pragma unroll 1
        for (int c = 0; c < CBLK; c++) {
            const int cin = cb + c;
            const float* base = &s_in[buf][c * SCH];
            u64 vv[3][PX + 2];
#pragma unroll
            for (int r = 0; r < 3; r++) {
                const float* rp = base + (ty + r) * SROW + tx * PX;
                const float* mp = MASK ? (s_m + (ty + r) * SROW + tx * PX) : nullptr;
#pragma unroll
                for (int j = 0; j < PX + 2; j++) {
                    float v = rp[j];
                    if (MASK) { if (domask) v *= mp[j]; }
                    vv[r][j] = pack2(v);
                }
            }
            const u64* wp = (const u64*)s_w + cin * 9 * NPAIR_TOT + z * NPH;
#pragma unroll
            for (int k = 0; k < 9; k++) {
                const int ky = k / 3, kx = k - ky * 3;
#pragma unroll
                for (int p = 0; p < NPH; p++) {
                    if (z == 0 || NPH + p < NPAIR_TOT) {
                        u64 w2 = wp[k * NPAIR_TOT + p];
#pragma unroll
                        for (int j = 0; j < PX; j++)
                            acc[p][j] = ffma2(w2, vv[ky][kx + j], acc[p][j]);
                    }
                }
            }
        }
    }

    const int y = y0 + ty, xbase = x0 + tx * PX;

    // epilogue: bias + activation + vector store (own pair range only)
#pragma unroll
    for (int p = 0; p < NPH; p++) {
        if (!(z == 0 || NPH + p < NPAIR_TOT)) continue;
        const int pi = z * NPH + p;
        const int co0 = 2 * pi, co1 = 2 * pi + 1;
        const float b0 = bias[co0];
        const float b1 = (co1 < COUT) ? bias[co1] : 0.f;
        float o0[PX], o1[PX];
#pragma unroll
        for (int j = 0; j < PX; j++) {
            float lo, hi; unpack2(acc[p][j], lo, hi);
            lo += b0; hi += b1;
            if (ACT == 1) { lo = fmaxf(lo, 0.f); hi = fmaxf(hi, 0.f); }
            else if (ACT == 2) { lo = 1.f / (1.f + expf(-lo)); hi = 1.f / (1.f + expf(-hi)); }
            o0[j] = lo; o1[j] = hi;
        }
        float* q0 = out + ((size_t)(b * cout_stride + co0) * HH + y) * WW + xbase;
        *(float4*)q0 = make_float4(o0[0], o0[1], o0[2], o0[3]);
        if (co1 < COUT) {
            float* q1 = out + ((size_t)(b * cout_stride + co1) * HH + y) * WW + xbase;
            *(float4*)q1 = make_float4(o1[0], o1[1], o1[2], o1[3]);
        }
    }
}

// ---- single-conv kernel (PX=4, no z-split) ----
template<int CIN, int COUT, int ACT, bool DUAL>
__global__ void __launch_bounds__(128, 4)
conv_k(const float* __restrict__ src0, const float* __restrict__ src1,
       const float* __restrict__ msk, const float* __restrict__ wg,
       const float* __restrict__ bias, float* __restrict__ out, int cout_stride)
{
    __shared__ __align__(16) char raw[SMEM_MAX];
    conv3x3_body<CIN, COUT, ACT, DUAL, false, false>(raw, src0, src1, msk, wg, bias,
                                                     out, cout_stride, blockIdx.z,
                                                     threadIdx.x, threadIdx.y, blockIdx.y);
}

// ---- z-split conv kernel (PX=4, cout halves across threadIdx.z) ----
template<int CIN, int COUT, int ACT, bool DUAL>
__global__ void __launch_bounds__(256, 2)
conv_kz(const float* __restrict__ src0, const float* __restrict__ src1,
        const float* __restrict__ msk, const float* __restrict__ wg,
        const float* __restrict__ bias, float* __restrict__ out, int cout_stride)
{
    __shared__ __align__(16) char raw[SMEM_MAX];
    conv3x3_body<CIN, COUT, ACT, DUAL, true, false>(raw, src0, src1, msk, wg, bias,
                                                    out, cout_stride, blockIdx.z,
                                                    threadIdx.x, threadIdx.y, blockIdx.y);
}

// ---- pair kernel: two independent convs in one launch (block-granular) ----
template<int CINA, int COUTA, int ACTA, bool DUALA, bool MASKA,
         int CINB, int COUTB, int ACTB, bool DUALB, bool MASKB>
__global__ void __launch_bounds__(128, 4)
conv_pair(const float* __restrict__ a0, const float* __restrict__ a1,
          const float* __restrict__ amsk,
          const float* __restrict__ aw, const float* __restrict__ ab,
          float* __restrict__ ao,
          const float* __restrict__ b0, const float* __restrict__ b1,
          const float* __restrict__ bmsk,
          const float* __restrict__ bw, const float* __restrict__ bb,
          float* __restrict__ bo)
{
    __shared__ __align__(16) char raw[SMEM_MAX];
    if (blockIdx.z < BB)
        conv3x3_body<CINA, COUTA, ACTA, DUALA, false, MASKA>(
            raw, a0, a1, amsk, aw, ab, ao, 16, blockIdx.z,
            threadIdx.x, threadIdx.y, blockIdx.y);
    else
        conv3x3_body<CINB, COUTB, ACTB, DUALB, false, MASKB>(
            raw, b0, b1, bmsk, bw, bb, bo, 16, blockIdx.z - BB,
            threadIdx.x, threadIdx.y, blockIdx.y);
}

// ============================================================================
// Modulated deformable conv 3x3 (torchvision semantics), stride 1, pad 1,
// fused sigmoid(mask) + ReLU epilogue. Planar coalesced gather, batched loads.
// ============================================================================
__global__ void __launch_bounds__(256)
deform_kernel(const float* __restrict__ fE,   // [B][16][H][W]
              const float* __restrict__ om,   // [B][27][H][W]
              const float* __restrict__ wg,   // [16][16][3][3]
              const float* __restrict__ bias, // [16]
              float* __restrict__ out)        // [B][16][H][W]
{
    __shared__ __align__(8) float s_w[16 * 9 * 16];  // [ci][tap][co]
    const int tid = threadIdx.y * 32 + threadIdx.x;
    for (int idx = tid; idx < 16 * 16 * 9; idx += 256) {
        int co = idx / 144;
        int r = idx - co * 144;
        int ci = r / 9, t = r - ci * 9;
        s_w[(ci * 9 + t) * 16 + co] = wg[idx];
    }
    __syncthreads();

    const int x = blockIdx.x * 32 + threadIdx.x;
    const int y = blockIdx.y * 8 + threadIdx.y;
    const int b = blockIdx.z;

    u64 acc[8];
#pragma unroll
    for (int p = 0; p < 8; p++) acc[p] = 0ull;

    const float* omb = om + (size_t)b * 27 * HWSZ + y * WW + x;
    const float* pE = fE + (size_t)b * 16 * HWSZ;

#pragma unroll 1
    for (int t = 0; t < 9; t++) {
        const float oy = omb[(2 * t) * HWSZ];
        const float ox = omb[(2 * t + 1) * HWSZ];
        const float mv = omb[(18 + t) * HWSZ];
        const float m = 1.f / (1.f + expf(-mv));
        const float py = (float)(y + t / 3 - 1) + oy;
        const float px = (float)(x + t % 3 - 1) + ox;
        const float fy = floorf(py), fx = floorf(px);
        const int y0 = (int)fy, x0 = (int)fx;
        const float dy = py - fy, dx = px - fx;
        float w00 = (1.f - dy) * (1.f - dx) * m;
        float w01 = (1.f - dy) * dx * m;
        float w10 = dy * (1.f - dx) * m;
        float w11 = dy * dx * m;
        const bool vy0 = (unsigned)y0 < HH, vy1 = (unsigned)(y0 + 1) < HH;
        const bool vx0 = (unsigned)x0 < WW, vx1 = (unsigned)(x0 + 1) < WW;
        if (!(vy0 && vx0)) w00 = 0.f;
        if (!(vy0 && vx1)) w01 = 0.f;
        if (!(vy1 && vx0)) w10 = 0.f;
        if (!(vy1 && vx1)) w11 = 0.f;
        const int y0c = min(max(y0, 0), HH - 1), y1c = min(max(y0 + 1, 0), HH - 1);
        const int x0c = min(max(x0, 0), WW - 1), x1c = min(max(x0 + 1, 0), WW - 1);
        const int i00 = y0c * WW + x0c, i01 = y0c * WW + x1c;
        const int i10 = y1c * WW + x0c, i11 = y1c * WW + x1c;

        float v00[16], v01[16], v10[16], v11[16];
#pragma unroll
        for (int ci = 0; ci < 16; ci++) {
            const float* pc = pE + ci * HWSZ;
            v00[ci] = pc[i00];
            v01[ci] = pc[i01];
            v10[ci] = pc[i10];
            v11[ci] = pc[i11];
        }

#pragma unroll
        for (int ci = 0; ci < 16; ci++) {
            const float s = w00 * v00[ci] + w01 * v01[ci]
                          + w10 * v10[ci] + w11 * v11[ci];
            const u64 ss = pack2(s);
            const u64* wrow = (const u64*)s_w + (ci * 9 + t) * 8;
#pragma unroll
            for (int p = 0; p < 8; p++)
                acc[p] = ffma2(wrow[p], ss, acc[p]);
        }
    }

#pragma unroll
    for (int p = 0; p < 8; p++) {
        float lo, hi; unpack2(acc[p], lo, hi);
        lo = fmaxf(lo + bias[2 * p], 0.f);
        hi = fmaxf(hi + bias[2 * p + 1], 0.f);
        out[((size_t)(b * 16 + 2 * p) * HH + y) * WW + x] = lo;
        out[((size_t)(b * 16 + 2 * p + 1) * HH + y) * WW + x] = hi;
    }
}

// ============================================================================
// Launch
// ============================================================================
extern "C" void kernel_launch(void* const* d_in, const int* in_sizes, int n_in,
                              void* d_out, int out_size)
{
    const float* fE = (const float*)d_in[0];
    const float* fF = (const float*)d_in[1];
    const float* sab_att_w1 = (const float*)d_in[2];
    const float* sab_att_b1 = (const float*)d_in[3];
    const float* sab_att_w2 = (const float*)d_in[4];
    const float* sab_att_b2 = (const float*)d_in[5];
    const float* sab_ref_w = (const float*)d_in[6];
    const float* sab_ref_b = (const float*)d_in[7];
    const float* om_w1 = (const float*)d_in[8];
    const float* om_b1 = (const float*)d_in[9];
    const float* om_w2 = (const float*)d_in[10];
    const float* om_b2 = (const float*)d_in[11];
    const float* om_w3 = (const float*)d_in[12];
    const float* om_b3 = (const float*)d_in[13];
    const float* dcb_w = (const float*)d_in[14];
    const float* dcb_b = (const float*)d_in[15];
    const float* dcbref_w = (const float*)d_in[16];
    const float* dcbref_b = (const float*)d_in[17];
    const float* fin_w = (const float*)d_in[18];
    const float* fin_b = (const float*)d_in[19];
    float* out = (float*)d_out;

    float *t1, *t2, *t3, *ME, *fEFsa, *fEdc, *fEFdc, *om;
    cudaGetSymbolAddress((void**)&t1, g_t1);
    cudaGetSymbolAddress((void**)&t2, g_t2);
    cudaGetSymbolAddress((void**)&t3, g_t3);
    cudaGetSymbolAddress((void**)&ME, g_ME);
    cudaGetSymbolAddress((void**)&fEFsa, g_fEFsa);
    cudaGetSymbolAddress((void**)&fEdc, g_fEdc);
    cudaGetSymbolAddress((void**)&fEFdc, g_fEFdc);
    cudaGetSymbolAddress((void**)&om, g_om);

    dim3 grid(WW / TILE_W, HH / TILE_H, BB);       // (8, 16, 4)
    dim3 gridP(WW / TILE_W, HH / TILE_H, 2 * BB);  // (8, 16, 8) pair launches
    dim3 blk4(TILE_W / 4, TILE_H);                 // 128
    dim3 blkZ(TILE_W / 4, TILE_H, 2);              // 256 (z-split)

    // P1: t1 = relu(conv(cat(fE,fF), sab_att_w1)) ; t2 = relu(conv(cat(fE,fF), om_w1))
    conv_pair<32, 16, 1, true, false, 32, 16, 1, true, false><<<gridP, blk4>>>(
        fE, fF, nullptr, sab_att_w1, sab_att_b1, t1,
        fE, fF, nullptr, om_w1, om_b1, t2);
    // k2: M_E = sigmoid(conv(t1, sab_att_w2))   [1 channel only — no fEsa materialization]
    conv_k<16, 1, 2, false><<<grid, blk4>>>(t1, nullptr, nullptr, sab_att_w2, sab_att_b2, ME, 1);
    // P2: f_EFsa = relu(conv(cat(fE*M_E, fF), sab_ref_w))  [mask at pack time]
    //     t3 = relu(conv(t2, om_w2))
    conv_pair<32, 16, 1, true, true, 16, 16, 1, false, false><<<gridP, blk4>>>(
        fE, fF, ME, sab_ref_w, sab_ref_b, fEFsa,
        t2, nullptr, nullptr, om_w2, om_b2, t3);
    // k6: om = conv(t3, om_w3)  [27 ch, no act] — PX=4 z-split
    conv_kz<16, 27, 0, false><<<grid, blkZ>>>(t3, nullptr, nullptr, om_w3, om_b3, om, 27);
    // deform: f_Edc = relu(deform_conv(fE, offsets, sigmoid(mask), dcb_w))
    deform_kernel<<<dim3(WW / 32, HH / 8, BB), dim3(32, 8)>>>(fE, om, dcb_w, dcb_b, fEdc);
    // k8: f_EFdc = relu(conv(cat(fEdc, fF), dcbref_w))
    conv_k<32, 16, 1, true><<<grid, blk4>>>(fEdc, fF, nullptr, dcbref_w, dcbref_b, fEFdc, 16);
    // k9: out = relu(conv(cat(fEFsa, fEFdc), fin_w))
    conv_k<32, 16, 1, true><<<grid, blk4>>>(fEFsa, fEFdc, nullptr, fin_w, fin_b, out, 16);
}